// round 17
// baseline (speedup 1.0000x reference)
#include <cuda_runtime.h>
#include <math.h>
#include <stdint.h>

#define EMB   1024
#define HS    64
#define TSEQ  4096
#define BATCH 4
#define MTOT  (BATCH * TSEQ)   // 16384 rows

#define NQT2   32              // 128-row q tiles per batch
#define CHUNK  8               // 64-row kv-tiles per partial job
#define NJOBS  144             // sum_{q=0}^{31} (q/4+1)
#define NJOBS_T (NJOBS * BATCH)

// Scratch (device globals: allocation-free rule)
__device__ unsigned short g_qh[MTOT * HS], g_ql[MTOT * HS];   // Q hi/lo bf16, natural
__device__ unsigned short g_kh[MTOT * HS], g_kl[MTOT * HS];   // K hi/lo bf16, natural
__device__ unsigned short g_vth[BATCH * HS * TSEQ];           // V hi bf16, transposed [b][h][t]
__device__ unsigned short g_vtl[BATCH * HS * TSEQ];           // V lo
__device__ float          g_vf32[MTOT * HS];                  // V fp32, natural [row][h]
__device__ unsigned short g_wth[3 * HS * EMB];                // W hi bf16, transposed [w][n][k]
__device__ unsigned short g_wtl[3 * HS * EMB];                // W lo
__device__ float g_po[NJOBS_T * 128 * HS];   // partial O [slot][row][64]
__device__ float g_pm[NJOBS_T * 128];        // partial row max
__device__ float g_pl[NJOBS_T * 128];        // partial row sum

// ---- bf16 split: pack (x,y) -> bf16x2 hi + lo residual ----
__device__ __forceinline__ void split2(float x, float y, unsigned &hp, unsigned &lp) {
    asm("cvt.rn.bf16x2.f32 %0, %1, %2;" : "=r"(hp) : "f"(y), "f"(x));
    float xh = __uint_as_float(hp << 16);
    float yh = __uint_as_float(hp & 0xffff0000u);
    asm("cvt.rn.bf16x2.f32 %0, %1, %2;" : "=r"(lp) : "f"(y - yh), "f"(x - xh));
}

// ---- warp mma m16n8k16 bf16 -> f32 accumulate ----
#define MMA_BF16(c, a, b0, b1) \
    asm("mma.sync.aligned.m16n8k16.row.col.f32.bf16.bf16.f32 " \
        "{%0,%1,%2,%3},{%4,%5,%6,%7},{%8,%9},{%0,%1,%2,%3};" \
        : "+f"((c)[0]), "+f"((c)[1]), "+f"((c)[2]), "+f"((c)[3]) \
        : "r"((a)[0]), "r"((a)[1]), "r"((a)[2]), "r"((a)[3]), "r"(b0), "r"(b1))

// ---- packed fp32x2 (exact per lane) for the fp32-pipe PV half ----
#define FMA2(d, a, b) \
    asm("fma.rn.f32x2 %0, %1, %2, %0;" : "+l"(d) : "l"(a), "l"(b))
#define MUL2(d, a) \
    asm("mul.rn.f32x2 %0, %0, %1;" : "+l"(d) : "l"(a))
#define PACK2(d, x) \
    asm("mov.b64 %0, {%1, %1};" : "=l"(d) : "r"(__float_as_uint(x)))
#define UNPACK2(x, y, d) do { \
    unsigned _lo, _hi; \
    asm("mov.b64 {%0, %1}, %2;" : "=r"(_lo), "=r"(_hi) : "l"(d)); \
    (x) = __uint_as_float(_lo); (y) = __uint_as_float(_hi); } while (0)

// ---- cp.async (16B) ----
#define CP_ASYNC16(s, g) \
    asm volatile("cp.async.cg.shared.global [%0], [%1], 16;" :: "r"(s), "l"(g))
#define CP_COMMIT() asm volatile("cp.async.commit_group;" ::: "memory")
#define CP_WAIT1()  asm volatile("cp.async.wait_group 1;" ::: "memory")
#define CP_WAIT0()  asm volatile("cp.async.wait_group 0;" ::: "memory")

__device__ __forceinline__ unsigned s2u(const void* p) {
    unsigned a;
    asm("{ .reg .u64 t; cvta.to.shared.u64 t, %1; cvt.u32.u64 %0, t; }"
        : "=r"(a) : "l"(p));
    return a;
}

// ---------------------------------------------------------------------------
// Kernel 0: split W into transposed bf16 hi/lo (verbatim).
// ---------------------------------------------------------------------------
__global__ __launch_bounds__(256) void wsplit_kernel(
    const float* __restrict__ Wq,
    const float* __restrict__ Wk,
    const float* __restrict__ Wv)
{
    int idx = blockIdx.x * 256 + threadIdx.x;
    if (idx >= 3 * EMB * HS) return;
    int w   = idx >> 16;
    int rem = idx & 65535;
    int k   = rem >> 6;
    int n   = rem & 63;
    const float* W = (w == 0) ? Wq : (w == 1) ? Wk : Wv;
    float x = W[k * HS + n];
    unsigned short h, l;
    asm("cvt.rn.bf16.f32 %0, %1;" : "=h"(h) : "f"(x));
    float xh = __uint_as_float(((unsigned)h) << 16);
    float xl = x - xh;
    asm("cvt.rn.bf16.f32 %0, %1;" : "=h"(l) : "f"(xl));
    g_wth[((size_t)w * HS + n) * EMB + k] = h;
    g_wtl[((size_t)w * HS + n) * EMB + k] = l;
}

// ---------------------------------------------------------------------------
// Kernel 1: fused QKV projection on tensor cores (R13 winner + fp32 V emit).
// ---------------------------------------------------------------------------
#define XKS 72
#define QKV_SMEM_BYTES ((2 * 64 * XKS + 2 * 3 * 64 * XKS) * 2)

__global__ __launch_bounds__(128, 2) void qkv_kernel(const float* __restrict__ X)
{
    extern __shared__ __align__(16) unsigned short sm[];
    unsigned short* Xh = sm;
    unsigned short* Xl = Xh + 64 * XKS;
    unsigned short* Wh = Xl + 64 * XKS;
    unsigned short* Wl = Wh + 3 * 64 * XKS;

    const int tid  = threadIdx.x;
    const int wid  = tid >> 5;
    const int lane = tid & 31;
    const int lq   = lane >> 2;
    const int lr   = lane & 3;
    const int m0   = blockIdx.x * 64;

    float c[3][8][4];
#pragma unroll
    for (int w3 = 0; w3 < 3; w3++)
#pragma unroll
        for (int nt = 0; nt < 8; nt++)
#pragma unroll
            for (int j = 0; j < 4; j++) c[w3][nt][j] = 0.0f;

    for (int k0 = 0; k0 < EMB; k0 += 64) {
#pragma unroll
        for (int t = 0; t < 8; t++) {
            int idx = tid + 128 * t;
            int row = idx >> 4;
            int cg  = idx & 15;
            float4 v = *(const float4*)&X[(size_t)(m0 + row) * EMB + k0 + 4 * cg];
            unsigned h01, l01, h23, l23;
            split2(v.x, v.y, h01, l01);
            split2(v.z, v.w, h23, l23);
            *(unsigned*)&Xh[row * XKS + 4 * cg]     = h01;
            *(unsigned*)&Xh[row * XKS + 4 * cg + 2] = h23;
            *(unsigned*)&Xl[row * XKS + 4 * cg]     = l01;
            *(unsigned*)&Xl[row * XKS + 4 * cg + 2] = l23;
        }
#pragma unroll
        for (int t = 0; t < 24; t++) {
            int idx  = tid + 128 * t;
            int wh   = idx >> 9;
            int w3   = wh >> 1;
            int half = wh & 1;
            int rem  = idx & 511;
            int n    = rem >> 3;
            int cc   = rem & 7;
            const unsigned short* src = half ? g_wtl : g_wth;
            unsigned short* dst = half ? Wl : Wh;
            *(float4*)&dst[(w3 * 64 + n) * XKS + 8 * cc] =
                *(const float4*)&src[((size_t)w3 * 64 + n) * EMB + k0 + 8 * cc];
        }
        __syncthreads();

        unsigned ah[4][4], al[4][4];
        int r = 16 * wid + lq;
#pragma unroll
        for (int ks = 0; ks < 4; ks++) {
            int col = 2 * lr + 16 * ks;
            ah[ks][0] = *(const unsigned*)&Xh[r * XKS + col];
            ah[ks][1] = *(const unsigned*)&Xh[(r + 8) * XKS + col];
            ah[ks][2] = *(const unsigned*)&Xh[r * XKS + col + 8];
            ah[ks][3] = *(const unsigned*)&Xh[(r + 8) * XKS + col + 8];
            al[ks][0] = *(const unsigned*)&Xl[r * XKS + col];
            al[ks][1] = *(const unsigned*)&Xl[(r + 8) * XKS + col];
            al[ks][2] = *(const unsigned*)&Xl[r * XKS + col + 8];
            al[ks][3] = *(const unsigned*)&Xl[(r + 8) * XKS + col + 8];
        }

#pragma unroll
        for (int w3 = 0; w3 < 3; w3++)
#pragma unroll
            for (int nt = 0; nt < 8; nt++)
#pragma unroll
                for (int ks = 0; ks < 4; ks++) {
                    int base = (w3 * 64 + 8 * nt + lq) * XKS + 2 * lr + 16 * ks;
                    unsigned bh0 = *(const unsigned*)&Wh[base];
                    unsigned bh1 = *(const unsigned*)&Wh[base + 8];
                    unsigned bl0 = *(const unsigned*)&Wl[base];
                    unsigned bl1 = *(const unsigned*)&Wl[base + 8];
                    MMA_BF16(c[w3][nt], ah[ks], bh0, bh1);
                    MMA_BF16(c[w3][nt], ah[ks], bl0, bl1);
                    MMA_BF16(c[w3][nt], al[ks], bh0, bh1);
                }
        __syncthreads();
    }

    const int r0 = m0 + 16 * wid + lq;
    const int bb = r0 >> 12;
    const int t0 = r0 & 4095;
#pragma unroll
    for (int nt = 0; nt < 8; nt++) {
        int n0 = 8 * nt + 2 * lr;
        unsigned hp, lp;
        split2(c[0][nt][0], c[0][nt][1], hp, lp);
        *(unsigned*)&g_qh[(size_t)r0 * HS + n0] = hp;
        *(unsigned*)&g_ql[(size_t)r0 * HS + n0] = lp;
        split2(c[0][nt][2], c[0][nt][3], hp, lp);
        *(unsigned*)&g_qh[(size_t)(r0 + 8) * HS + n0] = hp;
        *(unsigned*)&g_ql[(size_t)(r0 + 8) * HS + n0] = lp;
        split2(c[1][nt][0], c[1][nt][1], hp, lp);
        *(unsigned*)&g_kh[(size_t)r0 * HS + n0] = hp;
        *(unsigned*)&g_kl[(size_t)r0 * HS + n0] = lp;
        split2(c[1][nt][2], c[1][nt][3], hp, lp);
        *(unsigned*)&g_kh[(size_t)(r0 + 8) * HS + n0] = hp;
        *(unsigned*)&g_kl[(size_t)(r0 + 8) * HS + n0] = lp;
        // V bf16 hi/lo transposed [b][n][t]
        split2(c[2][nt][0], c[2][nt][1], hp, lp);
        g_vth[((size_t)bb * HS + n0) * TSEQ + t0]     = (unsigned short)hp;
        g_vth[((size_t)bb * HS + n0 + 1) * TSEQ + t0] = (unsigned short)(hp >> 16);
        g_vtl[((size_t)bb * HS + n0) * TSEQ + t0]     = (unsigned short)lp;
        g_vtl[((size_t)bb * HS + n0 + 1) * TSEQ + t0] = (unsigned short)(lp >> 16);
        split2(c[2][nt][2], c[2][nt][3], hp, lp);
        g_vth[((size_t)bb * HS + n0) * TSEQ + t0 + 8]     = (unsigned short)hp;
        g_vth[((size_t)bb * HS + n0 + 1) * TSEQ + t0 + 8] = (unsigned short)(hp >> 16);
        g_vtl[((size_t)bb * HS + n0) * TSEQ + t0 + 8]     = (unsigned short)lp;
        g_vtl[((size_t)bb * HS + n0 + 1) * TSEQ + t0 + 8] = (unsigned short)(lp >> 16);
        // V fp32 natural [row][h] (for the fp32-pipe PV half)
        *(float2*)&g_vf32[(size_t)r0 * HS + n0]       = make_float2(c[2][nt][0], c[2][nt][1]);
        *(float2*)&g_vf32[(size_t)(r0 + 8) * HS + n0] = make_float2(c[2][nt][2], c[2][nt][3]);
    }
}

// ---------------------------------------------------------------------------
// Kernel 2: split-KV flash attention, hybrid-pipe PV.
//  - S = Q@K^T : tensor (bf16x3), all 64 kv cols (unchanged)
//  - PV cols  0..31 : tensor (bf16x3) from Vt hi/lo rows 0..31
//  - PV cols 32..63 : fp32 FFMA2 pipe, P-fp32 smem x V-fp32 smem (exact)
// cp.async double-buffered staging. 256 threads, 2 CTAs/SM.
// ---------------------------------------------------------------------------
#define KST 72                            // ushort stride (144 B rows)
#define VFS 36                            // float stride of Vf32 rows (144 B)
#define PST 68                            // float stride of Ps rows
#define OFF_KH 0
#define OFF_KL 9216
#define OFF_VH 18432
#define OFF_VL 23040
#define OFF_VF 27648
#define BUFB   36864
#define OFF_PS (2 * BUFB)                 // 73728
#define OFF_AL (OFF_PS + 128 * PST * 4)   // 108544
#define ATTN_SMEM_BYTES (OFF_AL + 512)    // 109056

__global__ __launch_bounds__(256, 2) void attn_partial_kernel(void)
{
    extern __shared__ __align__(16) char smem[];
    const unsigned sbase = s2u(smem);
    float* Ps     = (float*)(smem + OFF_PS);
    float* alphaS = (float*)(smem + OFF_AL);

    const int b = blockIdx.x & 3;
    int rem = blockIdx.x >> 2;
    int q = 31;
    for (;;) { int nc = (q >> 2) + 1; if (rem < nc) break; rem -= nc; --q; }
    const int qt2 = q;
    const int ch = rem;
    const int kt0 = CHUNK * ch;
    const int kt1 = min(CHUNK * ch + CHUNK, 2 * qt2 + 2);
    int pre = 0;
    for (int qq = 31; qq > qt2; --qq) pre += (qq >> 2) + 1;
    const int slot = b * NJOBS + pre + ch;

    const int tid  = threadIdx.x;
    const int w    = tid >> 5;
    const int lane = tid & 31;
    const int lq   = lane >> 2;    // 0..7
    const int lr   = lane & 3;     // 0..3
    const int fty  = tid >> 3;     // 0..31 (fp32-path row group)
    const int ftx  = tid & 7;      // 0..7  (fp32-path col group)

    const size_t qrow0 = (size_t)b * TSEQ + qt2 * 128 + 16 * w + lq;
    const size_t kbase = (size_t)b * TSEQ;

    // ---- load Q fragments (hi/lo) once ----
    unsigned ah[4][4], al[4][4];
#pragma unroll
    for (int ks = 0; ks < 4; ks++) {
        int col = 2 * lr + 16 * ks;
        ah[ks][0] = *(const unsigned*)&g_qh[qrow0 * HS + col];
        ah[ks][1] = *(const unsigned*)&g_qh[(qrow0 + 8) * HS + col];
        ah[ks][2] = *(const unsigned*)&g_qh[qrow0 * HS + col + 8];
        ah[ks][3] = *(const unsigned*)&g_qh[(qrow0 + 8) * HS + col + 8];
        al[ks][0] = *(const unsigned*)&g_ql[qrow0 * HS + col];
        al[ks][1] = *(const unsigned*)&g_ql[(qrow0 + 8) * HS + col];
        al[ks][2] = *(const unsigned*)&g_ql[qrow0 * HS + col + 8];
        al[ks][3] = *(const unsigned*)&g_ql[(qrow0 + 8) * HS + col + 8];
    }

    float m0 = -1e30f, m1 = -1e30f, l0 = 0.0f, l1 = 0.0f;
    float o_[4][4];                      // tensor PV accum (cols 0..31)
    unsigned long long o2[4][2];         // fp32 PV accum (rows fty+32i, cols 32+4ftx..+3)
#pragma unroll
    for (int nt = 0; nt < 4; nt++)
#pragma unroll
        for (int j = 0; j < 4; j++) o_[nt][j] = 0.0f;
#pragma unroll
    for (int i = 0; i < 4; i++) { o2[i][0] = 0ull; o2[i][1] = 0ull; }

#define STAGE_TILE(bufsel, ktv) do {                                           \
    unsigned db = sbase + (bufsel) * BUFB;                                     \
    _Pragma("unroll")                                                          \
    for (int t = 0; t < 2; t++) {                                              \
        int idx = tid + 256 * t;                                               \
        int row = idx >> 3, cc = idx & 7;                                      \
        size_t kg = (kbase + (size_t)(ktv) * 64 + row) * HS + 8 * cc;          \
        CP_ASYNC16(db + OFF_KH + row * 144 + 16 * cc, (const char*)&g_kh[kg]); \
        CP_ASYNC16(db + OFF_KL + row * 144 + 16 * cc, (const char*)&g_kl[kg]); \
    }                                                                          \
    {                                                                          \
        int row = tid >> 3, cc = tid & 7;                                      \
        size_t vg = ((size_t)(b * HS + row)) * TSEQ + (size_t)(ktv) * 64 + 8 * cc; \
        CP_ASYNC16(db + OFF_VH + row * 144 + 16 * cc, (const char*)&g_vth[vg]);\
        CP_ASYNC16(db + OFF_VL + row * 144 + 16 * cc, (const char*)&g_vtl[vg]);\
    }                                                                          \
    _Pragma("unroll")                                                          \
    for (int t = 0; t < 2; t++) {                                              \
        int idx = tid + 256 * t;                                               \
        int row = idx >> 3, cc = idx & 7;                                      \
        const float* src = &g_vf32[(kbase + (size_t)(ktv) * 64 + row) * HS + 32 + 4 * cc]; \
        CP_ASYNC16(db + OFF_VF + row * 144 + 16 * cc, (const char*)src);       \
    }                                                                          \
} while (0)

    STAGE_TILE(0, kt0);
    CP_COMMIT();

    int buf = 0;
    for (int kt = kt0; kt < kt1; kt++) {
        if (kt + 1 < kt1) {
            STAGE_TILE(buf ^ 1, kt + 1);
            CP_COMMIT();
            CP_WAIT1();
        } else {
            CP_WAIT0();
        }
        __syncthreads();

        const unsigned short* Kh = (const unsigned short*)(smem + buf * BUFB + OFF_KH);
        const unsigned short* Kl = (const unsigned short*)(smem + buf * BUFB + OFF_KL);
        const unsigned short* Vh = (const unsigned short*)(smem + buf * BUFB + OFF_VH);
        const unsigned short* Vl = (const unsigned short*)(smem + buf * BUFB + OFF_VL);
        const float*          Vf = (const float*)(smem + buf * BUFB + OFF_VF);

        // ---- S = Q@K^T (bf16x3, all 8 n-tiles) ----
        float s[8][4];
#pragma unroll
        for (int nt = 0; nt < 8; nt++)
#pragma unroll
            for (int j = 0; j < 4; j++) s[nt][j] = 0.0f;

#pragma unroll
        for (int nt = 0; nt < 8; nt++) {
            int base = (8 * nt + lq) * KST + 2 * lr;
#pragma unroll
            for (int ks = 0; ks < 4; ks++) {
                int o = base + 16 * ks;
                unsigned bh0 = *(const unsigned*)&Kh[o];
                unsigned bh1 = *(const unsigned*)&Kh[o + 8];
                unsigned bl0 = *(const unsigned*)&Kl[o];
                unsigned bl1 = *(const unsigned*)&Kl[o + 8];
                MMA_BF16(s[nt], ah[ks], bh0, bh1);
                MMA_BF16(s[nt], ah[ks], bl0, bl1);
                MMA_BF16(s[nt], al[ks], bh0, bh1);
            }
        }

        // ---- causal mask ----
        if (kt >= 2 * qt2) {
            int off = (kt - 2 * qt2) * 64;
            int rl0 = 16 * w + lq;
            int rl1 = rl0 + 8;
#pragma unroll
            for (int nt = 0; nt < 8; nt++) {
                int cl = off + 8 * nt + 2 * lr;
                if (cl     > rl0) s[nt][0] = -1e30f;
                if (cl + 1 > rl0) s[nt][1] = -1e30f;
                if (cl     > rl1) s[nt][2] = -1e30f;
                if (cl + 1 > rl1) s[nt][3] = -1e30f;
            }
        }

        // ---- online softmax (rows r0, r0+8; quad-reduce) ----
        float mx0 = -1e30f, mx1 = -1e30f;
#pragma unroll
        for (int nt = 0; nt < 8; nt++) {
            mx0 = fmaxf(mx0, fmaxf(s[nt][0], s[nt][1]));
            mx1 = fmaxf(mx1, fmaxf(s[nt][2], s[nt][3]));
        }
#pragma unroll
        for (int off = 1; off < 4; off <<= 1) {
            mx0 = fmaxf(mx0, __shfl_xor_sync(0xffffffffu, mx0, off));
            mx1 = fmaxf(mx1, __shfl_xor_sync(0xffffffffu, mx1, off));
        }
        float mn0 = fmaxf(m0, mx0), mn1 = fmaxf(m1, mx1);
        float a0 = __expf(m0 - mn0), a1 = __expf(m1 - mn1);
        m0 = mn0; m1 = mn1;
        float ps0 = 0.0f, ps1 = 0.0f;
#pragma unroll
        for (int nt = 0; nt < 8; nt++) {
            s[nt][0] = __expf(s[nt][0] - mn0); ps0 += s[nt][0];
            s[nt][1] = __expf(s[nt][1] - mn0); ps0 += s[nt][1];
            s[nt][2] = __expf(s[nt][2] - mn1); ps1 += s[nt][2];
            s[nt][3] = __expf(s[nt][3] - mn1); ps1 += s[nt][3];
        }
#pragma unroll
        for (int off = 1; off < 4; off <<= 1) {
            ps0 += __shfl_xor_sync(0xffffffffu, ps0, off);
            ps1 += __shfl_xor_sync(0xffffffffu, ps1, off);
        }
        l0 = l0 * a0 + ps0;
        l1 = l1 * a1 + ps1;
#pragma unroll
        for (int nt = 0; nt < 4; nt++) {
            o_[nt][0] *= a0; o_[nt][1] *= a0;
            o_[nt][2] *= a1; o_[nt][3] *= a1;
        }

        // ---- publish P (fp32) + alpha for the fp32 path ----
        {
            int r0 = 16 * w + lq;
#pragma unroll
            for (int nt = 0; nt < 8; nt++) {
                int n = 8 * nt + 2 * lr;
                *(float2*)&Ps[r0 * PST + n]       = make_float2(s[nt][0], s[nt][1]);
                *(float2*)&Ps[(r0 + 8) * PST + n] = make_float2(s[nt][2], s[nt][3]);
            }
            if (lr == 0) {
                alphaS[r0]     = a0;
                alphaS[r0 + 8] = a1;
            }
        }

        // ---- re-pack P into tensor PV A-frags (bf16 hi/lo) ----
        unsigned ph[4][4], pl[4][4];
#pragma unroll
        for (int ks = 0; ks < 4; ks++) {
            split2(s[2 * ks][0],     s[2 * ks][1],     ph[ks][0], pl[ks][0]);
            split2(s[2 * ks][2],     s[2 * ks][3],     ph[ks][1], pl[ks][1]);
            split2(s[2 * ks + 1][0], s[2 * ks + 1][1], ph[ks][2], pl[ks][2]);
            split2(s[2 * ks + 1][2], s[2 * ks + 1][3], ph[ks][3], pl[ks][3]);
        }
        __syncthreads();

        // ---- tensor PV: cols 0..31 (nt 0..3) ----
#pragma unroll
        for (int nt = 0; nt < 4; nt++) {
            int base = (8 * nt + lq) * KST + 2 * lr;
#pragma unroll
            for (int ks = 0; ks < 4; ks++) {
                int o = base + 16 * ks;
                unsigned bh0 = *(const unsigned*)&Vh[o];
                unsigned bh1 = *(const unsigned*)&Vh[o + 8];
                unsigned bl0 = *(const unsigned*)&Vl[o];
                unsigned bl1 = *(const unsigned*)&Vl[o + 8];
                MMA_BF16(o_[nt], ph[ks], bh0, bh1);
                MMA_BF16(o_[nt], ph[ks], bl0, bl1);
                MMA_BF16(o_[nt], pl[ks], bh0, bh1);
            }
        }

        // ---- fp32 PV: cols 32..63, rows fty+32i (exact, FFMA2 pipe) ----
        {
            unsigned long long av;
#pragma unroll
            for (int i = 0; i < 4; i++) {
                float af = alphaS[fty + 32 * i];
                PACK2(av, af);
                MUL2(o2[i][0], av);
                MUL2(o2[i][1], av);
            }
#pragma unroll 8
            for (int j = 0; j < 64; j++) {
                ulonglong2 vv = *(const ulonglong2*)&Vf[j * VFS + 4 * ftx];
                unsigned long long pp[4];
#pragma unroll
                for (int i = 0; i < 4; i++) {
                    float pv = Ps[(fty + 32 * i) * PST + j];
                    PACK2(pp[i], pv);
                }
#pragma unroll
                for (int i = 0; i < 4; i++) {
                    FMA2(o2[i][0], pp[i], vv.x);
                    FMA2(o2[i][1], pp[i], vv.y);
                }
            }
        }
        __syncthreads();   // Ps/Vf reads done before next tile overwrites
        buf ^= 1;
    }
#undef STAGE_TILE

    // ---- write partials ----
    float* PO = g_po + (size_t)slot * 128 * HS;
    {
        int r0 = 16 * w + lq;
#pragma unroll
        for (int nt = 0; nt < 4; nt++) {
            int n = 8 * nt + 2 * lr;
            *(float2*)&PO[(size_t)r0 * HS + n]       = make_float2(o_[nt][0], o_[nt][1]);
            *(float2*)&PO[(size_t)(r0 + 8) * HS + n] = make_float2(o_[nt][2], o_[nt][3]);
        }
        if (lr == 0) {
            g_pm[(size_t)slot * 128 + r0]     = m0;
            g_pm[(size_t)slot * 128 + r0 + 8] = m1;
            g_pl[(size_t)slot * 128 + r0]     = l0;
            g_pl[(size_t)slot * 128 + r0 + 8] = l1;
        }
    }
#pragma unroll
    for (int i = 0; i < 4; i++) {
        float x0, x1, x2, x3;
        UNPACK2(x0, x1, o2[i][0]);
        UNPACK2(x2, x3, o2[i][1]);
        *(float4*)&PO[(size_t)(fty + 32 * i) * HS + 32 + 4 * ftx] =
            make_float4(x0, x1, x2, x3);
    }
}

// ---------------------------------------------------------------------------
// Kernel 3: combine partials + epilogue /(l*8). 1024 blocks (latency-bound).
// r = 16*z + tid>>3, n0 = (tid&7)*8.
// ---------------------------------------------------------------------------
__global__ __launch_bounds__(128) void attn_reduce_kernel(float* __restrict__ out)
{
    const int qt2 = blockIdx.x;
    const int b   = blockIdx.y;
    const int tid = threadIdx.x;
    const int r   = 16 * blockIdx.z + (tid >> 3);
    const int n0  = (tid & 7) * 8;

    const int nc = (qt2 >> 2) + 1;
    int pre = 0;
    for (int qq = 31; qq > qt2; --qq) pre += (qq >> 2) + 1;
    const int gslot = b * NJOBS + pre;

    float m = -1e30f;
    for (int c = 0; c < nc; c++)
        m = fmaxf(m, g_pm[(size_t)(gslot + c) * 128 + r]);

    float lsum = 0.0f;
    float acc[8];
#pragma unroll
    for (int t = 0; t < 8; t++) acc[t] = 0.0f;

    for (int c = 0; c < nc; c++) {
        int slot = gslot + c;
        float wgt = __expf(g_pm[(size_t)slot * 128 + r] - m);
        lsum = fmaf(wgt, g_pl[(size_t)slot * 128 + r], lsum);
        const float* PO = g_po + ((size_t)slot * 128 + r) * HS + n0;
#pragma unroll
        for (int t = 0; t < 2; t++) {
            float4 v = *(const float4*)&PO[4 * t];
            acc[4 * t + 0] = fmaf(wgt, v.x, acc[4 * t + 0]);
            acc[4 * t + 1] = fmaf(wgt, v.y, acc[4 * t + 1]);
            acc[4 * t + 2] = fmaf(wgt, v.z, acc[4 * t + 2]);
            acc[4 * t + 3] = fmaf(wgt, v.w, acc[4 * t + 3]);
        }
    }

    // /(l) for softmax, /8 for the reference's post-softmax /sqrt(HS) quirk
    const float inv = 1.0f / (lsum * 8.0f);
    float* O = out + ((size_t)b * TSEQ + qt2 * 128 + r) * HS + n0;
#pragma unroll
    for (int t = 0; t < 2; t++) {
        float4 v = make_float4(acc[4 * t + 0] * inv, acc[4 * t + 1] * inv,
                               acc[4 * t + 2] * inv, acc[4 * t + 3] * inv);
        *(float4*)&O[4 * t] = v;
    }
}

// ---------------------------------------------------------------------------
extern "C" void kernel_launch(void* const* d_in, const int* in_sizes, int n_in,
                              void* d_out, int out_size)
{
    const float* X  = (const float*)d_in[0];
    const float* Wq = (const float*)d_in[1];
    const float* Wk = (const float*)d_in[2];
    const float* Wv = (const float*)d_in[3];
    float* out = (float*)d_out;

    (void)in_sizes; (void)n_in; (void)out_size;

    // W split+transpose to bf16 hi/lo
    wsplit_kernel<<<(3 * EMB * HS + 255) / 256, 256>>>(Wq, Wk, Wv);

    // Fused QKV projection on tensor cores (+ fp32 V emit)
    cudaFuncSetAttribute(qkv_kernel,
                         cudaFuncAttributeMaxDynamicSharedMemorySize, QKV_SMEM_BYTES);
    qkv_kernel<<<MTOT / 64, 128, QKV_SMEM_BYTES>>>(X);

    // Flash attention partials (hybrid tensor + fp32-pipe PV)
    cudaFuncSetAttribute(attn_partial_kernel,
                         cudaFuncAttributeMaxDynamicSharedMemorySize, ATTN_SMEM_BYTES);
    attn_partial_kernel<<<NJOBS_T, 256, ATTN_SMEM_BYTES>>>();

    // Combine partials + epilogue (1024 blocks)
    dim3 g3(NQT2, BATCH, 8);
    attn_reduce_kernel<<<g3, 128>>>(out);
}